// round 1
// baseline (speedup 1.0000x reference)
#include <cuda_runtime.h>
#include <math.h>

#define B_   16
#define S_   64
#define T_   64
#define TM1_ 63
#define H_   512
#define H3_  1536
#define V_   32000
#define ME_  (B_*S_)     // 1024 encoder rows
#define MD_  (B_*TM1_)   // 1008 decoder rows

// ---------------- device scratch (no allocation allowed) ----------------
__device__ float g_emb_x[ME_*H_];       // gathered encoder embeddings
__device__ float g_emb_y[MD_*H_];       // gathered decoder embeddings
__device__ float g_gi_enc[ME_*H3_];     // x @ W_ih_e^T + b_ih_e, all steps
__device__ float g_gi_dec[MD_*H3_];     // y @ W_ih_d^T + b_ih_d, all steps
__device__ float g_enc_out[ME_*H_];     // encoder hidden states [b][s][h]
__device__ float g_hbuf[4][B_*H_];      // h double buffers (0,1 enc / 2,3 dec)
__device__ float g_attn[B_*H_];         // attention context per step
__device__ float g_dseq[MD_*H_];        // d vectors for all decoder steps
__device__ float g_rownll[MD_];         // per-row NLL

// ---------------- embedding gather ----------------
__global__ void embed_kernel(const int* __restrict__ x, const int* __restrict__ y,
                             const float* __restrict__ emb_enc,
                             const float* __restrict__ emb_dec) {
    int i = blockIdx.x * blockDim.x + threadIdx.x;
    const int n1 = ME_ * H_;
    const int n2 = MD_ * H_;
    if (i < n1) {
        int row = i / H_, h = i % H_;
        g_emb_x[i] = emb_enc[(long)x[row] * H_ + h];
    } else if (i < n1 + n2) {
        int j = i - n1;
        int row = j / H_, h = j % H_;
        int b = row / TM1_, t = row % TM1_;
        g_emb_y[j] = emb_dec[(long)y[b * T_ + t] * H_ + h];  // y[:, :-1]
    }
}

// ---------------- generic fp32 GEMM: C[M,N] = A[M,K] * Bw[N,K]^T + bias[N] ----------------
// a_sel: 0=g_emb_x 1=g_emb_y 2=g_dseq ; c_sel: 0=g_gi_enc 1=g_gi_dec 2=Cext
__global__ void sgemm_nt(int a_sel, const float* __restrict__ Bw,
                         const float* __restrict__ bias, float* __restrict__ Cext,
                         int c_sel, int M, int N, int K) {
    __shared__ float As[16][64];
    __shared__ float Bs[16][64];
    const float* A = (a_sel == 0) ? g_emb_x : (a_sel == 1) ? g_emb_y : g_dseq;
    float* C = (c_sel == 0) ? g_gi_enc : (c_sel == 1) ? g_gi_dec : Cext;

    int tx = threadIdx.x & 15;          // M direction (4 rows)
    int ty = threadIdx.x >> 4;          // N direction (4 cols)
    int m0 = blockIdx.y * 64, n0 = blockIdx.x * 64;

    int lr = threadIdx.x >> 2;          // 0..63 tile row
    int lc = (threadIdx.x & 3) * 4;     // 0,4,8,12 k offset

    float acc[4][4] = {};
    for (int kc = 0; kc < K; kc += 16) {
        float4 av = make_float4(0.f, 0.f, 0.f, 0.f);
        if (m0 + lr < M) av = *(const float4*)&A[(long)(m0 + lr) * K + kc + lc];
        As[lc + 0][lr] = av.x; As[lc + 1][lr] = av.y;
        As[lc + 2][lr] = av.z; As[lc + 3][lr] = av.w;
        float4 bv = *(const float4*)&Bw[(long)(n0 + lr) * K + kc + lc];
        Bs[lc + 0][lr] = bv.x; Bs[lc + 1][lr] = bv.y;
        Bs[lc + 2][lr] = bv.z; Bs[lc + 3][lr] = bv.w;
        __syncthreads();
#pragma unroll
        for (int k = 0; k < 16; k++) {
            float4 a = *(float4*)&As[k][tx * 4];
            float4 b = *(float4*)&Bs[k][ty * 4];
            acc[0][0] += a.x * b.x; acc[0][1] += a.x * b.y; acc[0][2] += a.x * b.z; acc[0][3] += a.x * b.w;
            acc[1][0] += a.y * b.x; acc[1][1] += a.y * b.y; acc[1][2] += a.y * b.z; acc[1][3] += a.y * b.w;
            acc[2][0] += a.z * b.x; acc[2][1] += a.z * b.y; acc[2][2] += a.z * b.z; acc[2][3] += a.z * b.w;
            acc[3][0] += a.w * b.x; acc[3][1] += a.w * b.y; acc[3][2] += a.w * b.z; acc[3][3] += a.w * b.w;
        }
        __syncthreads();
    }
#pragma unroll
    for (int j = 0; j < 4; j++) {
        float bj = bias[n0 + ty * 4 + j];
#pragma unroll
        for (int i = 0; i < 4; i++) {
            int row = m0 + tx * 4 + i;
            if (row < M) C[(long)row * N + n0 + ty * 4 + j] = acc[i][j] + bj;
        }
    }
}

// ---------------- fused GRU step: gh = h @ W_hh^T, gates, h update ----------------
// grid 64 (j-tiles of 8), block 128 (16 b x 8 jj). is_enc selects gi table + enc_out write.
__global__ void gru_step(int is_enc, int t, int first, int hin_sel, int hout_sel,
                         const float* __restrict__ Whh, const float* __restrict__ bhh) {
    __shared__ float h_s[64][17];    // [k][b], padded
    __shared__ float w_s[24][68];    // 3 gates x 8 j rows, 64 k, padded (16B-aligned rows)

    int tid = threadIdx.x;
    int b = tid & 15, jj = tid >> 4;
    int jbase = blockIdx.x * 8;
    const float* hin = g_hbuf[hin_sel];

    float acc0 = 0.f, acc1 = 0.f, acc2 = 0.f;
    for (int kc = 0; kc < H_; kc += 64) {
        for (int v = tid; v < 256; v += 128) {
            int row = v >> 4;
            int c4 = (v & 15) * 4;
            float4 hv = make_float4(0.f, 0.f, 0.f, 0.f);
            if (!first) hv = *(const float4*)&hin[row * H_ + kc + c4];
            h_s[c4 + 0][row] = hv.x; h_s[c4 + 1][row] = hv.y;
            h_s[c4 + 2][row] = hv.z; h_s[c4 + 3][row] = hv.w;
        }
        for (int v = tid; v < 384; v += 128) {
            int r = v >> 4;                // 0..23
            int c4 = (v & 15) * 4;
            int g = r >> 3, j = jbase + (r & 7);
            *(float4*)&w_s[r][c4] = *(const float4*)&Whh[(long)(g * H_ + j) * H_ + kc + c4];
        }
        __syncthreads();
        int r0 = jj, r1 = 8 + jj, r2 = 16 + jj;
#pragma unroll
        for (int k = 0; k < 64; k += 4) {
            float4 w0 = *(float4*)&w_s[r0][k];
            float4 w1 = *(float4*)&w_s[r1][k];
            float4 w2 = *(float4*)&w_s[r2][k];
            float h0 = h_s[k][b], h1 = h_s[k + 1][b], h2 = h_s[k + 2][b], h3 = h_s[k + 3][b];
            acc0 += w0.x * h0 + w0.y * h1 + w0.z * h2 + w0.w * h3;
            acc1 += w1.x * h0 + w1.y * h1 + w1.z * h2 + w1.w * h3;
            acc2 += w2.x * h0 + w2.y * h1 + w2.z * h2 + w2.w * h3;
        }
        __syncthreads();
    }

    int j = jbase + jj;
    const float* gi = is_enc ? (g_gi_enc + ((long)b * S_ + t) * H3_)
                             : (g_gi_dec + ((long)b * TM1_ + t) * H3_);
    float ir = gi[j], iz = gi[H_ + j], in_ = gi[2 * H_ + j];
    float hr = acc0 + bhh[j];
    float hz = acc1 + bhh[H_ + j];
    float hn = acc2 + bhh[2 * H_ + j];
    float r = 1.f / (1.f + expf(-(ir + hr)));
    float z = 1.f / (1.f + expf(-(iz + hz)));
    float n = tanhf(in_ + r * hn);
    float hprev = first ? 0.f : hin[b * H_ + j];
    float h = (1.f - z) * n + z * hprev;
    g_hbuf[hout_sel][b * H_ + j] = h;
    if (is_enc) g_enc_out[((long)b * S_ + t) * H_ + j] = h;
}

// ---------------- attention: scores, softmax, context (one CTA per batch) ----------------
__global__ void attn_kernel(int h_sel) {
    __shared__ float sc[64];
    int b = blockIdx.x;
    int tid = threadIdx.x;  // 256
    const float* enc = g_enc_out + (long)b * S_ * H_;
    const float* hb = g_hbuf[h_sel] + b * H_;

    int s = tid >> 2, q = tid & 3;
    {
        const float* e = enc + s * H_ + q * 128;
        const float* hq = hb + q * 128;
        float p = 0.f;
#pragma unroll
        for (int k = 0; k < 128; k += 4) {
            float4 ev = *(const float4*)&e[k];
            float4 hv = *(const float4*)&hq[k];
            p += ev.x * hv.x + ev.y * hv.y + ev.z * hv.z + ev.w * hv.w;
        }
        p += __shfl_xor_sync(0xffffffffu, p, 1);
        p += __shfl_xor_sync(0xffffffffu, p, 2);
        if (q == 0) sc[s] = p;
    }
    __syncthreads();
    if (tid < 32) {
        float a0 = sc[tid], a1 = sc[tid + 32];
        float m = fmaxf(a0, a1);
        for (int o = 16; o; o >>= 1) m = fmaxf(m, __shfl_xor_sync(0xffffffffu, m, o));
        float e0 = expf(a0 - m), e1 = expf(a1 - m);
        float ss = e0 + e1;
        for (int o = 16; o; o >>= 1) ss += __shfl_xor_sync(0xffffffffu, ss, o);
        sc[tid] = e0 / ss;
        sc[tid + 32] = e1 / ss;
    }
    __syncthreads();
    for (int k = tid; k < H_; k += 256) {
        float a = 0.f;
#pragma unroll
        for (int s2 = 0; s2 < 64; s2++) a += sc[s2] * enc[s2 * H_ + k];
        g_attn[b * H_ + k] = a;
    }
}

// ---------------- d = tanh(concat(h, attn) @ W_c^T + b_c) ----------------
// grid 64 (j-tiles of 8), block 128 (16 b x 8 jj)
__global__ void dstep_kernel(int t, int h_sel, const float* __restrict__ Wc,
                             const float* __restrict__ bc) {
    __shared__ float in_s[64][17];
    __shared__ float w_s[8][68];
    int tid = threadIdx.x;
    int b = tid & 15, jj = tid >> 4;
    int jbase = blockIdx.x * 8;
    const float* hb = g_hbuf[h_sel];

    float acc = 0.f;
    for (int kc = 0; kc < 2 * H_; kc += 64) {
        const float* src = (kc < H_) ? hb : g_attn;
        int ko = kc & (H_ - 1);
        for (int v = tid; v < 256; v += 128) {
            int row = v >> 4;
            int c4 = (v & 15) * 4;
            float4 hv = *(const float4*)&src[row * H_ + ko + c4];
            in_s[c4 + 0][row] = hv.x; in_s[c4 + 1][row] = hv.y;
            in_s[c4 + 2][row] = hv.z; in_s[c4 + 3][row] = hv.w;
        }
        {
            int r = tid >> 4;                // 0..7
            int c4 = (tid & 15) * 4;
            *(float4*)&w_s[r][c4] = *(const float4*)&Wc[(long)(jbase + r) * (2 * H_) + kc + c4];
        }
        __syncthreads();
#pragma unroll
        for (int k = 0; k < 64; k += 4) {
            float4 w = *(float4*)&w_s[jj][k];
            acc += w.x * in_s[k][b] + w.y * in_s[k + 1][b]
                 + w.z * in_s[k + 2][b] + w.w * in_s[k + 3][b];
        }
        __syncthreads();
    }
    int j = jbase + jj;
    g_dseq[((long)b * TM1_ + t) * H_ + j] = tanhf(acc + bc[j]);
}

// ---------------- loss: per-row NLL then deterministic reduce ----------------
__global__ void nll_rows(const float* __restrict__ logits, const int* __restrict__ y) {
    __shared__ float red[256];
    int row = blockIdx.x;
    int b = row / TM1_, t = row % TM1_;
    int tgt = y[b * T_ + t + 1];
    const float* L = logits + (long)row * V_;

    float m = -INFINITY;
    for (int i = threadIdx.x; i < V_; i += 256) m = fmaxf(m, L[i]);
    red[threadIdx.x] = m;
    __syncthreads();
    for (int o = 128; o; o >>= 1) {
        if (threadIdx.x < o) red[threadIdx.x] = fmaxf(red[threadIdx.x], red[threadIdx.x + o]);
        __syncthreads();
    }
    m = red[0];
    __syncthreads();

    float ss = 0.f;
    for (int i = threadIdx.x; i < V_; i += 256) ss += expf(L[i] - m);
    red[threadIdx.x] = ss;
    __syncthreads();
    for (int o = 128; o; o >>= 1) {
        if (threadIdx.x < o) red[threadIdx.x] += red[threadIdx.x + o];
        __syncthreads();
    }
    if (threadIdx.x == 0) g_rownll[row] = logf(red[0]) + m - L[tgt];
}

__global__ void loss_reduce(float* __restrict__ out) {
    __shared__ float red[256];
    float ss = 0.f;
    for (int i = threadIdx.x; i < MD_; i += 256) ss += g_rownll[i];
    red[threadIdx.x] = ss;
    __syncthreads();
    for (int o = 128; o; o >>= 1) {
        if (threadIdx.x < o) red[threadIdx.x] += red[threadIdx.x + o];
        __syncthreads();
    }
    if (threadIdx.x == 0) out[0] = red[0] / (float)MD_;
}

// ---------------- host ----------------
extern "C" void kernel_launch(void* const* d_in, const int* in_sizes, int n_in,
                              void* d_out, int out_size) {
    const int*   x       = (const int*)d_in[0];
    const int*   y       = (const int*)d_in[1];
    const float* emb_enc = (const float*)d_in[2];
    const float* W_ih_e  = (const float*)d_in[3];
    const float* W_hh_e  = (const float*)d_in[4];
    const float* b_ih_e  = (const float*)d_in[5];
    const float* b_hh_e  = (const float*)d_in[6];
    const float* emb_dec = (const float*)d_in[7];
    const float* W_ih_d  = (const float*)d_in[8];
    const float* W_hh_d  = (const float*)d_in[9];
    const float* b_ih_d  = (const float*)d_in[10];
    const float* b_hh_d  = (const float*)d_in[11];
    const float* W_c     = (const float*)d_in[12];
    const float* b_c     = (const float*)d_in[13];
    const float* W_out   = (const float*)d_in[14];
    const float* b_out   = (const float*)d_in[15];
    float* out = (float*)d_out;

    // 1. embeddings
    {
        int total = ME_ * H_ + MD_ * H_;
        embed_kernel<<<(total + 255) / 256, 256>>>(x, y, emb_enc, emb_dec);
    }

    // 2. input-side gate precompute (parallel over all timesteps)
    sgemm_nt<<<dim3(H3_ / 64, ME_ / 64), 256>>>(0, W_ih_e, b_ih_e, nullptr, 0, ME_, H3_, H_);
    sgemm_nt<<<dim3(H3_ / 64, (MD_ + 63) / 64), 256>>>(1, W_ih_d, b_ih_d, nullptr, 1, MD_, H3_, H_);

    // 3. encoder recurrence
    for (int t = 0; t < S_; t++) {
        int first = (t == 0);
        int hin_sel = (t + 1) & 1;   // ignored when first
        int hout_sel = t & 1;
        gru_step<<<64, 128>>>(1, t, first, hin_sel, hout_sel, W_hh_e, b_hh_e);
    }
    int enc_final = (S_ - 1) & 1;    // = 1

    // 4. decoder recurrence
    for (int t = 0; t < TM1_; t++) {
        int hin_sel = (t == 0) ? enc_final : 2 + ((t + 1) & 1);
        int hout_sel = 2 + (t & 1);
        gru_step<<<64, 128>>>(0, t, 0, hin_sel, hout_sel, W_hh_d, b_hh_d);
        attn_kernel<<<B_, 256>>>(hout_sel);
        dstep_kernel<<<64, 128>>>(t, hout_sel, W_c, b_c);
    }

    // 5. logits = d @ W_out^T + b_out, directly into d_out
    sgemm_nt<<<dim3(V_ / 64, (MD_ + 63) / 64), 256>>>(2, W_out, b_out, out, 2, MD_, V_, H_);

    // 6. loss (written after the logits block, if the output includes it)
    if (out_size >= MD_ * V_ + 1) {
        nll_rows<<<MD_, 256>>>(out, y);
        loss_reduce<<<1, 256>>>(out + (long)MD_ * V_);
    }
}

// round 2
// speedup vs baseline: 2.5598x; 2.5598x over previous
#include <cuda_runtime.h>
#include <math.h>

#define B_   16
#define S_   64
#define T_   64
#define TM1_ 63
#define H_   512
#define H3_  1536
#define V_   32000
#define ME_  (B_*S_)     // 1024 encoder rows
#define MD_  (B_*TM1_)   // 1008 decoder rows
#define NCTA 128

// ---------------- device scratch (no allocation allowed) ----------------
__device__ float g_emb_x[ME_*H_];       // gathered encoder embeddings
__device__ float g_emb_y[MD_*H_];       // gathered decoder embeddings
__device__ float g_gi_enc[ME_*H3_];     // x @ W_ih_e^T + b_ih_e, all steps
__device__ float g_gi_dec[MD_*H3_];     // y @ W_ih_d^T + b_ih_d, all steps
__device__ float g_enc_out[ME_*H_];     // encoder hidden states [b][s][h]
__device__ float g_h[2][B_*H_];         // h ping-pong for recurrence
__device__ float g_cat[MD_*2*H_];       // [row][1024] = concat(h_dec, attn)
__device__ float g_dseq[MD_*H_];        // d vectors for all decoder steps
__device__ float g_rownll[MD_];         // per-row NLL

__device__ unsigned g_cnt = 0;
__device__ unsigned g_gen = 0;

// ---------------- software grid barrier (all NCTA CTAs co-resident) ----------------
__device__ __forceinline__ void grid_bar() {
    __threadfence();                       // make this thread's STGs visible
    __syncthreads();
    if (threadIdx.x == 0) {
        unsigned g = *(volatile unsigned*)&g_gen;
        if (atomicAdd(&g_cnt, 1u) == NCTA - 1) {
            g_cnt = 0;
            __threadfence();
            atomicExch(&g_gen, g + 1u);
        } else {
            while (*(volatile unsigned*)&g_gen == g) __nanosleep(32);
        }
        __threadfence();                   // gpu-scope fence -> L1 invalidate for this SM
    }
    __syncthreads();
}

// ---------------- embedding gather ----------------
__global__ void embed_kernel(const int* __restrict__ x, const int* __restrict__ y,
                             const float* __restrict__ emb_enc,
                             const float* __restrict__ emb_dec) {
    int i = blockIdx.x * blockDim.x + threadIdx.x;
    const int n1 = ME_ * H_;
    const int n2 = MD_ * H_;
    if (i < n1) {
        int row = i / H_, h = i % H_;
        g_emb_x[i] = emb_enc[(long)x[row] * H_ + h];
    } else if (i < n1 + n2) {
        int j = i - n1;
        int row = j / H_, h = j % H_;
        int b = row / TM1_, t = row % TM1_;
        g_emb_y[j] = emb_dec[(long)y[b * T_ + t] * H_ + h];  // y[:, :-1]
    }
}

// ---------------- generic fp32 GEMM: C[M,N] = act(A[M,K] * Bw[N,K]^T + bias[N]) ----------------
// a_sel: 0=g_emb_x 1=g_emb_y 2=g_dseq 3=g_cat ; c_sel: 0=g_gi_enc 1=g_gi_dec 2=Cext 3=g_dseq
__global__ void sgemm_nt(int a_sel, const float* __restrict__ Bw,
                         const float* __restrict__ bias, float* __restrict__ Cext,
                         int c_sel, int M, int N, int K, int act) {
    __shared__ float As[16][64];
    __shared__ float Bs[16][64];
    const float* A = (a_sel == 0) ? g_emb_x : (a_sel == 1) ? g_emb_y
                   : (a_sel == 2) ? g_dseq : g_cat;
    float* C = (c_sel == 0) ? g_gi_enc : (c_sel == 1) ? g_gi_dec
             : (c_sel == 2) ? Cext : g_dseq;

    int tx = threadIdx.x & 15;          // M direction (4 rows)
    int ty = threadIdx.x >> 4;          // N direction (4 cols)
    int m0 = blockIdx.y * 64, n0 = blockIdx.x * 64;

    int lr = threadIdx.x >> 2;          // 0..63 tile row
    int lc = (threadIdx.x & 3) * 4;     // 0,4,8,12 k offset

    float acc[4][4] = {};
    for (int kc = 0; kc < K; kc += 16) {
        float4 av = make_float4(0.f, 0.f, 0.f, 0.f);
        if (m0 + lr < M) av = *(const float4*)&A[(long)(m0 + lr) * K + kc + lc];
        As[lc + 0][lr] = av.x; As[lc + 1][lr] = av.y;
        As[lc + 2][lr] = av.z; As[lc + 3][lr] = av.w;
        float4 bv = *(const float4*)&Bw[(long)(n0 + lr) * K + kc + lc];
        Bs[lc + 0][lr] = bv.x; Bs[lc + 1][lr] = bv.y;
        Bs[lc + 2][lr] = bv.z; Bs[lc + 3][lr] = bv.w;
        __syncthreads();
#pragma unroll
        for (int k = 0; k < 16; k++) {
            float4 a = *(float4*)&As[k][tx * 4];
            float4 b = *(float4*)&Bs[k][ty * 4];
            acc[0][0] += a.x * b.x; acc[0][1] += a.x * b.y; acc[0][2] += a.x * b.z; acc[0][3] += a.x * b.w;
            acc[1][0] += a.y * b.x; acc[1][1] += a.y * b.y; acc[1][2] += a.y * b.z; acc[1][3] += a.y * b.w;
            acc[2][0] += a.z * b.x; acc[2][1] += a.z * b.y; acc[2][2] += a.z * b.z; acc[2][3] += a.z * b.w;
            acc[3][0] += a.w * b.x; acc[3][1] += a.w * b.y; acc[3][2] += a.w * b.z; acc[3][3] += a.w * b.w;
        }
        __syncthreads();
    }
#pragma unroll
    for (int j = 0; j < 4; j++) {
        float bj = bias[n0 + ty * 4 + j];
#pragma unroll
        for (int i = 0; i < 4; i++) {
            int row = m0 + tx * 4 + i;
            if (row < M) {
                float v = acc[i][j] + bj;
                if (act) v = tanhf(v);
                C[(long)row * N + n0 + ty * 4 + j] = v;
            }
        }
    }
}

// ---------------- persistent GRU recurrence (enc 64 steps + dec 63 steps) ----------------
// 128 CTAs x 256 threads. CTA owns j-slice [cta*4, cta*4+4) of H for all 3 gates.
// Weights for both directions resident in smem for the whole kernel.
// Thread = (b, jj, ks): b=tid&15, jj=(tid>>4)&3, ks=tid>>6 (k-range ks*128..+128).
__global__ void __launch_bounds__(256, 1)
recurrence_kernel(const float* __restrict__ Whh_e, const float* __restrict__ bhh_e,
                  const float* __restrict__ Whh_d, const float* __restrict__ bhh_d) {
    extern __shared__ float sm[];
    float* we  = sm;                     // [3][4][512] = 6144 floats
    float* wd  = we + 3 * 4 * H_;        // 6144 floats
    float* hs  = wd + 3 * 4 * H_;        // [16][516] padded = 8256 floats
    float* red = hs + 16 * 516;          // [4 ks][3 g][64 (jj*16+b)] = 768 floats

    const int tid = threadIdx.x;
    const int cta = blockIdx.x;
    const int jbase = cta * 4;

    // load weight slices once (float4)
    for (int v = tid; v < 12 * 128; v += 256) {
        int r = v >> 7, c = v & 127;
        int g = r >> 2, jj = r & 3;
        long src = ((long)(g * H_ + jbase + jj) * H_) / 4 + c;
        ((float4*)we)[(long)r * 128 + c] = ((const float4*)Whh_e)[src];
        ((float4*)wd)[(long)r * 128 + c] = ((const float4*)Whh_d)[src];
    }

    const int b  = tid & 15;
    const int jj = (tid >> 4) & 3;
    const int ks = tid >> 6;
    const int k0 = ks * 128;
    const int j  = jbase + jj;

    const float be0 = bhh_e[j], be1 = bhh_e[H_ + j], be2 = bhh_e[2 * H_ + j];
    const float bd0 = bhh_d[j], bd1 = bhh_d[H_ + j], bd2 = bhh_d[2 * H_ + j];

    // zero h stage for step 0
    for (int v = tid; v < 16 * 516; v += 256) hs[v] = 0.f;

    int cur = 0;
    for (int step = 0; step < 127; step++) {
        const int enc = (step < 64);
        const int t = enc ? step : step - 64;

        if (step > 0) {
            // stage h[cur] (coalesced float4)
            for (int v = tid; v < 2048; v += 256) {
                int bb = v >> 7, cc = v & 127;
                float4 hv = ((const float4*)g_h[cur])[v];
                *(float4*)&hs[bb * 516 + cc * 4] = hv;
            }
        }
        // prefetch gi for this (b,j) — only ks==0 consumes
        float gi0 = 0.f, gi1 = 0.f, gi2 = 0.f;
        {
            const float* gi = enc ? &g_gi_enc[(long)(b * S_ + t) * H3_]
                                  : &g_gi_dec[(long)(b * TM1_ + t) * H3_];
            if (ks == 0) { gi0 = gi[j]; gi1 = gi[H_ + j]; gi2 = gi[2 * H_ + j]; }
        }
        __syncthreads();

        const float* wsel = enc ? we : wd;
        const float* hb = &hs[b * 516 + k0];
        const float* w0 = &wsel[(0 * 4 + jj) * H_ + k0];
        const float* w1 = &wsel[(1 * 4 + jj) * H_ + k0];
        const float* w2 = &wsel[(2 * 4 + jj) * H_ + k0];
        float a0 = 0.f, a1 = 0.f, a2 = 0.f;
#pragma unroll
        for (int k = 0; k < 128; k += 4) {
            float4 h4 = *(const float4*)&hb[k];
            float4 x0 = *(const float4*)&w0[k];
            float4 x1 = *(const float4*)&w1[k];
            float4 x2 = *(const float4*)&w2[k];
            a0 += x0.x * h4.x + x0.y * h4.y + x0.z * h4.z + x0.w * h4.w;
            a1 += x1.x * h4.x + x1.y * h4.y + x1.z * h4.z + x1.w * h4.w;
            a2 += x2.x * h4.x + x2.y * h4.y + x2.z * h4.z + x2.w * h4.w;
        }
        int slot = jj * 16 + b;
        red[(ks * 3 + 0) * 64 + slot] = a0;
        red[(ks * 3 + 1) * 64 + slot] = a1;
        red[(ks * 3 + 2) * 64 + slot] = a2;
        __syncthreads();

        if (ks == 0) {
            float s0 = red[0 * 64 + slot] + red[3 * 64 + slot] + red[6 * 64 + slot] + red[9 * 64 + slot];
            float s1 = red[1 * 64 + slot] + red[4 * 64 + slot] + red[7 * 64 + slot] + red[10 * 64 + slot];
            float s2 = red[2 * 64 + slot] + red[5 * 64 + slot] + red[8 * 64 + slot] + red[11 * 64 + slot];
            float hr = s0 + (enc ? be0 : bd0);
            float hz = s1 + (enc ? be1 : bd1);
            float hn = s2 + (enc ? be2 : bd2);
            float r = 1.f / (1.f + expf(-(gi0 + hr)));
            float z = 1.f / (1.f + expf(-(gi1 + hz)));
            float n = tanhf(gi2 + r * hn);
            float hprev = hs[b * 516 + j];
            float h = (1.f - z) * n + z * hprev;
            g_h[cur ^ 1][b * H_ + j] = h;
            if (enc) g_enc_out[(long)(b * S_ + t) * H_ + j] = h;
            else     g_cat[(long)(b * TM1_ + t) * 2 * H_ + j] = h;
        }
        cur ^= 1;
        if (step != 126) grid_bar();
    }
}

// ---------------- batched attention: one CTA per (b,t) decoder row ----------------
__global__ void attn_batch() {
    __shared__ float hsh[H_];
    __shared__ float sc[S_];
    __shared__ float wgt[S_];
    int row = blockIdx.x;               // b*63 + t
    int b = row / TM1_;
    int tid = threadIdx.x;              // 256
    const float* enc = g_enc_out + (long)b * S_ * H_;
    const float* hrow = &g_cat[(long)row * 2 * H_];

    for (int v = tid; v < H_; v += 256) hsh[v] = hrow[v];
    __syncthreads();

    int s = tid >> 2, q = tid & 3;
    {
        const float* e = enc + s * H_ + q * 128;
        const float* hq = hsh + q * 128;
        float p = 0.f;
#pragma unroll
        for (int k = 0; k < 128; k += 4) {
            float4 ev = *(const float4*)&e[k];
            float4 hv = *(const float4*)&hq[k];
            p += ev.x * hv.x + ev.y * hv.y + ev.z * hv.z + ev.w * hv.w;
        }
        p += __shfl_xor_sync(0xffffffffu, p, 1);
        p += __shfl_xor_sync(0xffffffffu, p, 2);
        if (q == 0) sc[s] = p;
    }
    __syncthreads();
    if (tid < 32) {
        float a0 = sc[tid], a1 = sc[tid + 32];
        float m = fmaxf(a0, a1);
        for (int o = 16; o; o >>= 1) m = fmaxf(m, __shfl_xor_sync(0xffffffffu, m, o));
        float e0 = expf(a0 - m), e1 = expf(a1 - m);
        float ss = e0 + e1;
        for (int o = 16; o; o >>= 1) ss += __shfl_xor_sync(0xffffffffu, ss, o);
        wgt[tid] = e0 / ss;
        wgt[tid + 32] = e1 / ss;
    }
    __syncthreads();
    {
        int k = tid, k2 = tid + 256;
        float acc = 0.f, acc2 = 0.f;
#pragma unroll 8
        for (int s2 = 0; s2 < S_; s2++) {
            float w = wgt[s2];
            acc  += w * enc[s2 * H_ + k];
            acc2 += w * enc[s2 * H_ + k2];
        }
        g_cat[(long)row * 2 * H_ + H_ + k]  = acc;
        g_cat[(long)row * 2 * H_ + H_ + k2] = acc2;
    }
}

// ---------------- loss: per-row NLL then deterministic reduce ----------------
__global__ void nll_rows(const float* __restrict__ logits, const int* __restrict__ y) {
    __shared__ float red[256];
    int row = blockIdx.x;
    int b = row / TM1_, t = row % TM1_;
    int tgt = y[b * T_ + t + 1];
    const float* L = logits + (long)row * V_;

    float m = -INFINITY;
    for (int i = threadIdx.x; i < V_; i += 256) m = fmaxf(m, L[i]);
    red[threadIdx.x] = m;
    __syncthreads();
    for (int o = 128; o; o >>= 1) {
        if (threadIdx.x < o) red[threadIdx.x] = fmaxf(red[threadIdx.x], red[threadIdx.x + o]);
        __syncthreads();
    }
    m = red[0];
    __syncthreads();

    float ss = 0.f;
    for (int i = threadIdx.x; i < V_; i += 256) ss += expf(L[i] - m);
    red[threadIdx.x] = ss;
    __syncthreads();
    for (int o = 128; o; o >>= 1) {
        if (threadIdx.x < o) red[threadIdx.x] += red[threadIdx.x + o];
        __syncthreads();
    }
    if (threadIdx.x == 0) g_rownll[row] = logf(red[0]) + m - L[tgt];
}

__global__ void loss_reduce(float* __restrict__ out) {
    __shared__ float red[256];
    float ss = 0.f;
    for (int i = threadIdx.x; i < MD_; i += 256) ss += g_rownll[i];
    red[threadIdx.x] = ss;
    __syncthreads();
    for (int o = 128; o; o >>= 1) {
        if (threadIdx.x < o) red[threadIdx.x] += red[threadIdx.x + o];
        __syncthreads();
    }
    if (threadIdx.x == 0) out[0] = red[0] / (float)MD_;
}

// ---------------- host ----------------
extern "C" void kernel_launch(void* const* d_in, const int* in_sizes, int n_in,
                              void* d_out, int out_size) {
    const int*   x       = (const int*)d_in[0];
    const int*   y       = (const int*)d_in[1];
    const float* emb_enc = (const float*)d_in[2];
    const float* W_ih_e  = (const float*)d_in[3];
    const float* W_hh_e  = (const float*)d_in[4];
    const float* b_ih_e  = (const float*)d_in[5];
    const float* b_hh_e  = (const float*)d_in[6];
    const float* emb_dec = (const float*)d_in[7];
    const float* W_ih_d  = (const float*)d_in[8];
    const float* W_hh_d  = (const float*)d_in[9];
    const float* b_ih_d  = (const float*)d_in[10];
    const float* b_hh_d  = (const float*)d_in[11];
    const float* W_c     = (const float*)d_in[12];
    const float* b_c     = (const float*)d_in[13];
    const float* W_out   = (const float*)d_in[14];
    const float* b_out   = (const float*)d_in[15];
    float* out = (float*)d_out;

    // 1. embeddings
    {
        int total = ME_ * H_ + MD_ * H_;
        embed_kernel<<<(total + 255) / 256, 256>>>(x, y, emb_enc, emb_dec);
    }

    // 2. input-side gate precompute (parallel over all timesteps)
    sgemm_nt<<<dim3(H3_ / 64, ME_ / 64), 256>>>(0, W_ih_e, b_ih_e, nullptr, 0, ME_, H3_, H_, 0);
    sgemm_nt<<<dim3(H3_ / 64, (MD_ + 63) / 64), 256>>>(1, W_ih_d, b_ih_d, nullptr, 1, MD_, H3_, H_, 0);

    // 3. persistent recurrence (encoder + decoder GRU chain, weights smem-resident)
    {
        const int smem = (3 * 4 * H_ * 2 + 16 * 516 + 768) * sizeof(float); // 85248 B
        cudaFuncSetAttribute(recurrence_kernel,
                             cudaFuncAttributeMaxDynamicSharedMemorySize, smem);
        recurrence_kernel<<<NCTA, 256, smem>>>(W_hh_e, b_hh_e, W_hh_d, b_hh_d);
    }

    // 4. batched attention for all 1008 decoder rows
    attn_batch<<<MD_, 256>>>();

    // 5. d = tanh(concat(h, attn) @ W_c^T + b_c)  -> g_dseq
    sgemm_nt<<<dim3(H_ / 64, (MD_ + 63) / 64), 256>>>(3, W_c, b_c, nullptr, 3, MD_, H_, 2 * H_, 1);

    // 6. logits = d @ W_out^T + b_out, directly into d_out
    sgemm_nt<<<dim3(V_ / 64, (MD_ + 63) / 64), 256>>>(2, W_out, b_out, out, 2, MD_, V_, H_, 0);

    // 7. loss
    if (out_size >= MD_ * V_ + 1) {
        nll_rows<<<MD_, 256>>>(out, y);
        loss_reduce<<<1, 256>>>(out + (long)MD_ * V_);
    }
}